// round 16
// baseline (speedup 1.0000x reference)
#include <cuda_runtime.h>
#include <math.h>

#define D_MODEL   3072
#define NUM_E     8
#define N_TOKENS  16384
#define TPW       4                       // tokens per warp-quad
#define WARPS_PB  16
#define THREADS   (WARPS_PB * 32)         // 512
#define CHUNK_D   128                     // floats of D per stage
#define NCHUNK    (D_MODEL / CHUNK_D)     // 24 (divisible by PF=2)
#define PF        2                       // register prefetch depth
#define GRID      148
#define NWARPS_G  (GRID * WARPS_PB)       // 2368
#define NQUADS    (N_TOKENS / TPW)        // 4096
#define ROW_F4    (D_MODEL / 4)           // 768 float4 per token row
#define SMEM_BYTES (NUM_E * D_MODEL * 4)  // 96 KB paired-transposed W

typedef unsigned long long u64;

__device__ __forceinline__ u64 ffma2(u64 a, u64 b, u64 c) {
    u64 d;
    asm("fma.rn.f32x2 %0, %1, %2, %3;" : "=l"(d) : "l"(a), "l"(b), "l"(c));
    return d;
}
__device__ __forceinline__ u64 addf2(u64 a, u64 b) {
    u64 d;
    asm("add.rn.f32x2 %0, %1, %2;" : "=l"(d) : "l"(a), "l"(b));
    return d;
}
__device__ __forceinline__ u64 dup2(float f) {
    u64 r; unsigned u = __float_as_uint(f);
    asm("mov.b64 %0, {%1, %1};" : "=l"(r) : "r"(u));
    return r;
}
__device__ __forceinline__ u64 shflx64(u64 v, int m) {
    unsigned lo = (unsigned)v, hi = (unsigned)(v >> 32);
    lo = __shfl_xor_sync(0xFFFFFFFFu, lo, m);
    hi = __shfl_xor_sync(0xFFFFFFFFu, hi, m);
    return ((u64)hi << 32) | lo;
}
// Paired-transposed W (numerics verified R10/R15): row d holds e0..e7 (32 B);
// 16B-granule XOR swizzle -> conflict-free LDS.128.
__device__ __forceinline__ unsigned wt_off(int d, int h) {
    unsigned o = (unsigned)d * 32u + (unsigned)h * 16u;
    return o ^ ((((unsigned)d >> 2) & 7u) << 4);
}

__global__ void __launch_bounds__(THREADS, 1)
gating_kernel(const float* __restrict__ x,
              const float* __restrict__ W,
              const float* __restrict__ b,
              float* __restrict__ out,
              int idx_off)
{
    extern __shared__ char sWt[];   // 96 KB paired W

    for (int d = threadIdx.x; d < D_MODEL; d += THREADS) {
        #pragma unroll
        for (int e = 0; e < NUM_E; ++e) {
            float v = W[e * D_MODEL + d];
            *reinterpret_cast<float*>(sWt + wt_off(d, e >> 2) + (e & 3) * 4) = v;
        }
    }
    __syncthreads();

    const int warp = threadIdx.x >> 5;
    const int lane = threadIdx.x & 31;
    const int bid  = blockIdx.x;

    // R4-proven persistent schedule: quads q0 and maybe q0 + 2368.
    const int q0 = bid + GRID * warp;                 // < 2368
    const int nq = (q0 + NWARPS_G < NQUADS) ? 2 : 1;

    const size_t QSTRIDE_F4 = (size_t)NWARPS_G * (TPW * ROW_F4);
    const float4* cur =
        reinterpret_cast<const float4*>(x + (size_t)q0 * (TPW * D_MODEL)) + lane;

    float4 xpf[PF][TPW];   // 32 regs: 2-deep register prefetch

    #define ISSUE(base_, c_, slot_)                                           \
        do {                                                                  \
            const float4* _s = (base_) + (c_) * (CHUNK_D / 4);                \
            _Pragma("unroll")                                                 \
            for (int _tt = 0; _tt < TPW; ++_tt)                               \
                xpf[(slot_)][_tt] = __ldcs(_s + _tt * ROW_F4);                \
        } while (0)

    u64 acc[TPW][4];   // per token: (e0,e1),(e2,e3),(e4,e5),(e6,e7)
    #pragma unroll
    for (int t = 0; t < TPW; ++t)
        #pragma unroll
        for (int p = 0; p < 4; ++p)
            acc[t][p] = 0ull;

    // Prologue: 2 stages of x in flight.
    ISSUE(cur, 0, 0);
    ISSUE(cur, 1, 1);

    for (int j = 0; j < nq; ++j) {
        const float4* nxt = cur + QSTRIDE_F4;
        const bool more = (j + 1 < nq);

        #pragma unroll
        for (int c = 0; c < NCHUNK; ++c) {
            const int slot = c & 1;               // static: 24 % 2 == 0
            const int dbase = c * CHUNK_D + lane * 4;

            // One K-step per float4 component.
            #define KSTEP(k_, comp_)                                           \
                do {                                                           \
                    const ulonglong2 w01 =                                     \
                        *reinterpret_cast<const ulonglong2*>(                  \
                            sWt + wt_off(dbase + (k_), 0));                    \
                    const ulonglong2 w45 =                                     \
                        *reinterpret_cast<const ulonglong2*>(                  \
                            sWt + wt_off(dbase + (k_), 1));                    \
                    _Pragma("unroll")                                          \
                    for (int _tt = 0; _tt < TPW; ++_tt) {                      \
                        const u64 a = dup2(xpf[slot][_tt].comp_);              \
                        acc[_tt][0] = ffma2(a, w01.x, acc[_tt][0]);            \
                        acc[_tt][1] = ffma2(a, w01.y, acc[_tt][1]);            \
                        acc[_tt][2] = ffma2(a, w45.x, acc[_tt][2]);            \
                        acc[_tt][3] = ffma2(a, w45.y, acc[_tt][3]);            \
                    }                                                          \
                } while (0)

            KSTEP(0, x);
            KSTEP(1, y);
            KSTEP(2, z);
            KSTEP(3, w);
            #undef KSTEP

            // Refill the just-consumed slot with stage c+2.
            if (c < NCHUNK - PF) {
                ISSUE(cur, c + PF, slot);
            } else if (more) {
                ISSUE(nxt, c + PF - NCHUNK, slot);
            }
        }

        // ---- epilogue for quad q0 + j*NWARPS_G ----
        {
            const int tok0 = (q0 + j * NWARPS_G) * TPW;

            #pragma unroll
            for (int off = 16; off > 0; off >>= 1)
                #pragma unroll
                for (int tt = 0; tt < TPW; ++tt)
                    #pragma unroll
                    for (int p = 0; p < 4; ++p)
                        acc[tt][p] = addf2(acc[tt][p], shflx64(acc[tt][p], off));

            if (lane < TPW) {
                const int tok = tok0 + lane;

                float logit[NUM_E];
                #pragma unroll
                for (int p = 0; p < 4; ++p) {
                    logit[2 * p]     = __uint_as_float((unsigned)acc[lane][p])
                                       + __ldg(&b[2 * p]);
                    logit[2 * p + 1] = __uint_as_float((unsigned)(acc[lane][p] >> 32))
                                       + __ldg(&b[2 * p + 1]);
                }

                float m = logit[0];
                #pragma unroll
                for (int e = 1; e < NUM_E; ++e) m = fmaxf(m, logit[e]);

                float ex[NUM_E], Z = 0.0f;
                #pragma unroll
                for (int e = 0; e < NUM_E; ++e) { ex[e] = __expf(logit[e] - m); Z += ex[e]; }
                const float invZ = 1.0f / Z;

                float sc[NUM_E];
                #pragma unroll
                for (int e = 0; e < NUM_E; ++e) sc[e] = ex[e] * invZ;

                int i1 = 0;
                #pragma unroll
                for (int e = 1; e < NUM_E; ++e) if (sc[e] > sc[i1]) i1 = e;
                int i2 = (i1 == 0) ? 1 : 0;
                #pragma unroll
                for (int e = 0; e < NUM_E; ++e)
                    if (e != i1 && sc[e] > sc[i2]) i2 = e;

                const float v1 = sc[i1];
                const float v2 = sc[i2];
                const float e2 = __expf(v2 - v1);
                const float r1 = 1.0f / (1.0f + e2);
                const float r2 = 1.0f - r1;

                out[(size_t)tok * 2 + 0] = r1;
                out[(size_t)tok * 2 + 1] = r2;
                out[(size_t)idx_off + (size_t)tok * 2 + 0] = (float)i1;
                out[(size_t)idx_off + (size_t)tok * 2 + 1] = (float)i2;
            }

            // Reset accumulators for the next quad.
            #pragma unroll
            for (int tt = 0; tt < TPW; ++tt)
                #pragma unroll
                for (int p = 0; p < 4; ++p)
                    acc[tt][p] = 0ull;
        }

        cur = nxt;
    }
    #undef ISSUE
}

extern "C" void kernel_launch(void* const* d_in, const int* in_sizes, int n_in,
                              void* d_out, int out_size)
{
    const float* x = (const float*)d_in[0];
    const float* W = (const float*)d_in[1];
    const float* b = (const float*)d_in[2];
    float* out = (float*)d_out;

    const int idx_off = out_size / 2;

    cudaFuncSetAttribute(gating_kernel,
                         cudaFuncAttributeMaxDynamicSharedMemorySize,
                         (int)SMEM_BYTES);

    gating_kernel<<<GRID, THREADS, SMEM_BYTES>>>(x, W, b, out, idx_off);
}